// round 10
// baseline (speedup 1.0000x reference)
#include <cuda_runtime.h>
#include <cstdint>
#include <cstddef>

// Problem constants
#define BB 2
#define SS 2048
#define DD 1024
#define HH 16
#define HDD 64
#define DM 256  // D/4

// Scratch (device globals — no runtime allocation allowed)
// g_q: tf32 bits pre-scaled by 0.125; g_k/g_v: tf32 bits; g_hid/g_x: tf32 bits.
__device__ float g_q[BB*HH*SS*HDD];
__device__ float g_k[BB*HH*SS*HDD];
__device__ float g_v[BB*HH*SS*HDD];
__device__ float g_attn[BB*HH*SS*HDD];
__device__ float g_hid[BB*SS*DM];
__device__ float g_x[BB*SS*DD];
// tf32-rounded operands (prepass)
__device__ float g_wq[DD*DD];
__device__ float g_wk[DD*DD];
__device__ float g_wv[DD*DD];
__device__ float g_wo[DD*DD];
__device__ float g_wm1[DM*DD];
__device__ float g_wm2[DD*DM];
__device__ float g_qr[BB*SS*DD];

// ===========================================================================
// Helpers (arch-agnostic PTX only: mma.sync tf32, cp.async — no tcgen05!)
// ===========================================================================
__device__ __forceinline__ uint32_t smem_u32(const void* p) {
    uint32_t a;
    asm("{ .reg .u64 t; cvta.to.shared.u64 t, %1; cvt.u32.u64 %0, t; }"
        : "=r"(a) : "l"(p));
    return a;
}

__device__ __forceinline__ uint32_t f2tf(float f) {
    uint32_t u;
    asm("cvt.rna.tf32.f32 %0, %1;" : "=r"(u) : "f"(f));
    return u;
}

// D += A @ B  (m16n8k8 tf32, A row-major, B col-major)
__device__ __forceinline__ void mma_tf32(float (&d)[4], const uint32_t (&a)[4],
                                         const uint32_t (&b)[2]) {
    asm volatile(
        "mma.sync.aligned.m16n8k8.row.col.f32.tf32.tf32.f32 "
        "{%0,%1,%2,%3}, {%4,%5,%6,%7}, {%8,%9}, {%0,%1,%2,%3};"
        : "+f"(d[0]), "+f"(d[1]), "+f"(d[2]), "+f"(d[3])
        : "r"(a[0]), "r"(a[1]), "r"(a[2]), "r"(a[3]), "r"(b[0]), "r"(b[1]));
}

__device__ __forceinline__ void cp16(uint32_t dst, const void* src) {
    asm volatile("cp.async.ca.shared.global [%0], [%1], 16;"
                 :: "r"(dst), "l"(src));
}
#define CP_COMMIT() asm volatile("cp.async.commit_group;" ::: "memory")
#define CP_WAIT1()  asm volatile("cp.async.wait_group 1;"  ::: "memory")
#define CP_WAIT0()  asm volatile("cp.async.wait_group 0;"  ::: "memory")

// ===========================================================================
// Prepass: round 7 fp32 arrays to tf32 bits (RNA) in ONE launch.
// Segments (uint4 units): wq,wk,wv,wo (256K each), wm1,wm2 (64K), qr (1M).
// ===========================================================================
#define SEG_W  (DD*DD/4)     // 262144
#define SEG_M  (DM*DD/4)     // 65536
#define SEG_Q  (BB*SS*DD/4)  // 1048576
#define SEG_TOT (4*SEG_W + 2*SEG_M + SEG_Q)

__global__ void round_all_kernel(
    const float* __restrict__ s0, const float* __restrict__ s1,
    const float* __restrict__ s2, const float* __restrict__ s3,
    const float* __restrict__ s4, const float* __restrict__ s5,
    const float* __restrict__ s6,
    float* __restrict__ d0, float* __restrict__ d1,
    float* __restrict__ d2, float* __restrict__ d3,
    float* __restrict__ d4, float* __restrict__ d5,
    float* __restrict__ d6)
{
    int i = blockIdx.x * blockDim.x + threadIdx.x;
    if (i >= SEG_TOT) return;
    const float* src; float* dst;
    if      (i < SEG_W)              { src = s0; dst = d0; }
    else if (i < 2*SEG_W)            { src = s1; dst = d1; i -= SEG_W; }
    else if (i < 3*SEG_W)            { src = s2; dst = d2; i -= 2*SEG_W; }
    else if (i < 4*SEG_W)            { src = s3; dst = d3; i -= 3*SEG_W; }
    else if (i < 4*SEG_W + SEG_M)    { src = s4; dst = d4; i -= 4*SEG_W; }
    else if (i < 4*SEG_W + 2*SEG_M)  { src = s5; dst = d5; i -= 4*SEG_W + SEG_M; }
    else                             { src = s6; dst = d6; i -= 4*SEG_W + 2*SEG_M; }
    float4 v = ((const float4*)src)[i];
    ((uint4*)dst)[i] = make_uint4(f2tf(v.x), f2tf(v.y), f2tf(v.z), f2tf(v.w));
}

// ===========================================================================
// tf32 MMA GEMM: C[M,N] = A[M,K] @ W[N,K]^T + bias[N]
// A and W PRE-ROUNDED tf32 bits. 128x128 CTA tile, 8 warps (32x64 warp tile),
// BK=32 double-buffered cp.async (dynamic smem 64KB, 2 CTAs/SM), vectorized
// LDS.128 fragment loads via k-permutation.
// relu: ReLU. split: head-split layout. conv != 0: store f2tf(val*conv).
// gate: epilogue x = (attn*asc + abi)*(1 + mod*gate4) -> tf32 bits (C=g_x).
// ===========================================================================
#define GBK 32
#define GTILE (128*GBK)
#define GEMM_SMEM_BYTES (4*GTILE*4)   // As[2] + Bs[2]

__global__ void __launch_bounds__(256, 2) gemm_mma_kernel(
    const float* __restrict__ A, const float* __restrict__ W,
    const float* __restrict__ bias, float* __restrict__ C,
    int M, int N, int K, int relu, int split, float conv, int gate,
    const float* __restrict__ dop, const float* __restrict__ ser,
    const float* __restrict__ nor, const float* __restrict__ ace,
    const float* __restrict__ asc, const float* __restrict__ abi)
{
    extern __shared__ float gsm[];
    float* As0 = gsm;
    float* As1 = gsm + GTILE;
    float* Bs0 = gsm + 2*GTILE;
    float* Bs1 = gsm + 3*GTILE;

    const int tid = threadIdx.x;
    const int wid = tid >> 5;
    const int lane = tid & 31;
    const int gr = lane >> 2;       // group row 0..7
    const int tc = lane & 3;        // thread col 0..3
    const int warp_m = wid & 3;     // 4 warps along M
    const int warp_n = wid >> 2;    // 2 warps along N
    const int m0 = blockIdx.y << 7;
    const int n0 = blockIdx.x << 7;

    const uint32_t sA[2] = { smem_u32(As0), smem_u32(As1) };
    const uint32_t sB[2] = { smem_u32(Bs0), smem_u32(Bs1) };
    const float* Abuf[2] = { As0, As1 };
    const float* Bbuf[2] = { Bs0, Bs1 };

    float acc[2][8][4];
    #pragma unroll
    for (int mi = 0; mi < 2; mi++)
        #pragma unroll
        for (int nj = 0; nj < 8; nj++)
            #pragma unroll
            for (int q = 0; q < 4; q++) acc[mi][nj][q] = 0.f;

    const int KB = K >> 5;

    // 128 rows x 32 floats per matrix = 1024 cp16 -> 4 per thread per matrix
    auto issue = [&](int kb, int buf) {
        #pragma unroll
        for (int i = 0; i < 4; i++) {
            const int ch = tid + (i << 8);       // 0..1023
            const int row = ch >> 3, c8 = ch & 7;
            cp16(sA[buf] + (uint32_t)(row*GBK + c8*4)*4,
                 A + (size_t)(m0 + row)*K + kb*GBK + c8*4);
            cp16(sB[buf] + (uint32_t)(row*GBK + c8*4)*4,
                 W + (size_t)(n0 + row)*K + kb*GBK + c8*4);
        }
    };

    issue(0, 0);
    CP_COMMIT();

    for (int kb = 0; kb < KB; kb++) {
        const int buf = kb & 1;
        if (kb + 1 < KB) issue(kb + 1, buf ^ 1);
        CP_COMMIT();
        CP_WAIT1();
        __syncthreads();

        const uint32_t* a_s = (const uint32_t*)Abuf[buf];
        const uint32_t* b_s = (const uint32_t*)Bbuf[buf];

        #pragma unroll
        for (int ks = 0; ks < GBK; ks += 16) {
            uint4 a4[2][2];
            #pragma unroll
            for (int mi = 0; mi < 2; mi++) {
                const int r = warp_m*32 + mi*16 + gr;
                a4[mi][0] = *(const uint4*)(a_s + r*GBK + ks + 4*tc);
                a4[mi][1] = *(const uint4*)(a_s + (r+8)*GBK + ks + 4*tc);
            }
            uint32_t af0[2][4], af1[2][4];
            #pragma unroll
            for (int mi = 0; mi < 2; mi++) {
                af0[mi][0] = a4[mi][0].x; af0[mi][1] = a4[mi][1].x;
                af0[mi][2] = a4[mi][0].z; af0[mi][3] = a4[mi][1].z;
                af1[mi][0] = a4[mi][0].y; af1[mi][1] = a4[mi][1].y;
                af1[mi][2] = a4[mi][0].w; af1[mi][3] = a4[mi][1].w;
            }
            #pragma unroll
            for (int nj = 0; nj < 8; nj++) {
                const int n = warp_n*64 + nj*8 + gr;
                uint4 b4 = *(const uint4*)(b_s + n*GBK + ks + 4*tc);
                uint32_t bf0[2] = { b4.x, b4.z };
                uint32_t bf1[2] = { b4.y, b4.w };
                mma_tf32(acc[0][nj], af0[0], bf0);
                mma_tf32(acc[1][nj], af0[1], bf0);
                mma_tf32(acc[0][nj], af1[0], bf1);
                mma_tf32(acc[1][nj], af1[1], bf1);
            }
        }
        __syncthreads();
    }

    // Epilogue
    float gate4 = 0.f, ascv = 0.f, abiv = 0.f;
    if (gate) {
        gate4 = 0.25f * (dop[0] + ser[0] + nor[0] + ace[0]);
        ascv = asc[0];
        abiv = abi[0];
    }
    #pragma unroll
    for (int mi = 0; mi < 2; mi++) {
        const int row = m0 + warp_m*32 + mi*16 + gr;
        #pragma unroll
        for (int nj = 0; nj < 8; nj++) {
            const int col = n0 + warp_n*64 + nj*8 + 2*tc;
            const float b0 = bias[col], b1 = bias[col+1];
            float2 v0 = make_float2(acc[mi][nj][0] + b0, acc[mi][nj][1] + b1);
            float2 v1 = make_float2(acc[mi][nj][2] + b0, acc[mi][nj][3] + b1);
            if (relu) {
                v0.x = fmaxf(v0.x, 0.f); v0.y = fmaxf(v0.y, 0.f);
                v1.x = fmaxf(v1.x, 0.f); v1.y = fmaxf(v1.y, 0.f);
            }
            if (gate) {
                // mod -> x = (attn*asc + abi) * (1 + mod*gate4), tf32 bits
                const int b = row >> 11, s = row & (SS - 1);
                const int h = col >> 6, hd = col & 63;
                const int rb = (row+8) >> 11, rs = (row+8) & (SS - 1);
                float2 a0 = *(const float2*)(g_attn +
                    (((size_t)(b*HH + h))*SS + s)*HDD + hd);
                float2 a1 = *(const float2*)(g_attn +
                    (((size_t)(rb*HH + h))*SS + rs)*HDD + hd);
                v0.x = __uint_as_float(f2tf((a0.x*ascv + abiv)*(1.f + v0.x*gate4)));
                v0.y = __uint_as_float(f2tf((a0.y*ascv + abiv)*(1.f + v0.y*gate4)));
                v1.x = __uint_as_float(f2tf((a1.x*ascv + abiv)*(1.f + v1.x*gate4)));
                v1.y = __uint_as_float(f2tf((a1.y*ascv + abiv)*(1.f + v1.y*gate4)));
            } else if (conv != 0.f) {
                v0.x = __uint_as_float(f2tf(v0.x * conv));
                v0.y = __uint_as_float(f2tf(v0.y * conv));
                v1.x = __uint_as_float(f2tf(v1.x * conv));
                v1.y = __uint_as_float(f2tf(v1.y * conv));
            }
            if (split) {
                const int b = row >> 11, s = row & (SS - 1);
                const int h = col >> 6, hd = col & 63;
                float* d0 = C + (((size_t)(b*HH + h))*SS + s)*HDD + hd;
                const int rb = (row+8) >> 11, rs = (row+8) & (SS - 1);
                float* d1 = C + (((size_t)(rb*HH + h))*SS + rs)*HDD + hd;
                *(float2*)d0 = v0;
                *(float2*)d1 = v1;
            } else {
                *(float2*)(C + (size_t)row*N + col) = v0;
                *(float2*)(C + (size_t)(row+8)*N + col) = v1;
            }
        }
    }
}

// ===========================================================================
// Flash attention, tf32 MMA, P fully register-resident (no P smem),
// vectorized K fragment loads, cp.async double buffer, 1 sync per tile.
// smem: Kd[2][64*80]  Vd[2][64*68]  (strides conflict-free)
// ===========================================================================
#define KP 80
#define VP 68
#define KTILE (64*KP)
#define VTILE (64*VP)
#define ATT_SMEM_BYTES ((2*KTILE + 2*VTILE)*4)

__global__ void __launch_bounds__(256, 2) attn_mma_kernel()
{
    extern __shared__ float sm[];
    float* Kd = sm;                 // [2][64*KP] tf32 bits
    float* Vd = sm + 2*KTILE;       // [2][64*VP] tf32 bits

    const int tid = threadIdx.x;
    const int wid = tid >> 5;
    const int lane = tid & 31;
    const int gr = lane >> 2;
    const int tc = lane & 3;

    const int bh = blockIdx.y;
    const int m0 = blockIdx.x << 7;
    const float* Qg = g_q + (size_t)bh * SS * HDD;
    const float* Kg = g_k + (size_t)bh * SS * HDD;
    const float* Vg = g_v + (size_t)bh * SS * HDD;
    float*       Og = g_attn + (size_t)bh * SS * HDD;

    const uint32_t sK = smem_u32(Kd);
    const uint32_t sV = smem_u32(Vd);

    auto issue_kv = [&](int kt, int buf) {
        const int kbase = kt << 6;
        #pragma unroll
        for (int i = 0; i < 4; i++) {
            const int ch = tid + (i << 8);          // 0..1023
            const int row = ch >> 4, c16 = ch & 15;
            const size_t soff = (size_t)(kbase + row)*HDD + c16*4;
            cp16(sK + (uint32_t)(buf*KTILE + row*KP + c16*4)*4, Kg + soff);
            cp16(sV + (uint32_t)(buf*VTILE + row*VP + c16*4)*4, Vg + soff);
        }
    };

    // Q fragments (tf32 bits, pre-scaled), permuted hd mapping
    uint32_t qa[8][4];
    {
        const uint32_t* q0 = (const uint32_t*)(Qg + (size_t)(m0 + wid*16 + gr) * HDD);
        const uint32_t* q1 = q0 + 8 * HDD;
        #pragma unroll
        for (int g = 0; g < 4; g++) {
            uint4 ua = *(const uint4*)(q0 + 16*g + 4*tc);
            uint4 ub = *(const uint4*)(q1 + 16*g + 4*tc);
            qa[2*g][0]   = ua.x; qa[2*g+1][0] = ua.y;
            qa[2*g][2]   = ua.z; qa[2*g+1][2] = ua.w;
            qa[2*g][1]   = ub.x; qa[2*g+1][1] = ub.y;
            qa[2*g][3]   = ub.z; qa[2*g+1][3] = ub.w;
        }
    }

    float m0s = -1e30f, m1s = -1e30f, l0s = 0.f, l1s = 0.f;
    float o[8][4];
    #pragma unroll
    for (int nj = 0; nj < 8; nj++)
        #pragma unroll
        for (int q = 0; q < 4; q++) o[nj][q] = 0.f;

    issue_kv(0, 0);
    CP_COMMIT();

    const int NT = SS / 64;
    for (int kt = 0; kt < NT; kt++) {
        const int buf = kt & 1;
        CP_WAIT0();
        __syncthreads();
        if (kt + 1 < NT) { issue_kv(kt + 1, buf ^ 1); CP_COMMIT(); }

        const float* Ks = Kd + buf*KTILE;
        const float* Vs = Vd + buf*VTILE;

        // S = Q @ K^T (warp: 16 rows x 64 keys), vectorized B loads
        float sacc[8][4];
        #pragma unroll
        for (int nj = 0; nj < 8; nj++)
            #pragma unroll
            for (int q = 0; q < 4; q++) sacc[nj][q] = 0.f;
        #pragma unroll
        for (int nj = 0; nj < 8; nj++) {
            const uint32_t* krow = (const uint32_t*)(Ks + (nj*8 + gr)*KP);
            #pragma unroll
            for (int g = 0; g < 4; g++) {
                uint4 kb = *(const uint4*)(krow + 16*g + 4*tc);
                uint32_t bf0[2] = { kb.x, kb.z };
                uint32_t bf1[2] = { kb.y, kb.w };
                mma_tf32(sacc[nj], qa[2*g],   bf0);
                mma_tf32(sacc[nj], qa[2*g+1], bf1);
            }
        }

        // Register online softmax (rows gr -> elems 0,1; gr+8 -> 2,3)
        float mx0 = -1e30f, mx1 = -1e30f;
        #pragma unroll
        for (int nj = 0; nj < 8; nj++) {
            mx0 = fmaxf(mx0, fmaxf(sacc[nj][0], sacc[nj][1]));
            mx1 = fmaxf(mx1, fmaxf(sacc[nj][2], sacc[nj][3]));
        }
        mx0 = fmaxf(mx0, __shfl_xor_sync(0xffffffffu, mx0, 1));
        mx0 = fmaxf(mx0, __shfl_xor_sync(0xffffffffu, mx0, 2));
        mx1 = fmaxf(mx1, __shfl_xor_sync(0xffffffffu, mx1, 1));
        mx1 = fmaxf(mx1, __shfl_xor_sync(0xffffffffu, mx1, 2));

        const float mn0 = fmaxf(m0s, mx0);
        const float mn1 = fmaxf(m1s, mx1);
        const float c0 = __expf(m0s - mn0);
        const float c1 = __expf(m1s - mn1);
        float s0 = 0.f, s1 = 0.f;

        #pragma unroll
        for (int nj = 0; nj < 8; nj++) {
            const float p00 = __expf(sacc[nj][0] - mn0);
            const float p01 = __expf(sacc[nj][1] - mn0);
            const float p10 = __expf(sacc[nj][2] - mn1);
            const float p11 = __expf(sacc[nj][3] - mn1);
            s0 += p00 + p01;
            s1 += p10 + p11;
            sacc[nj][0] = __uint_as_float(f2tf(p00));
            sacc[nj][1] = __uint_as_float(f2tf(p01));
            sacc[nj][2] = __uint_as_float(f2tf(p10));
            sacc[nj][3] = __uint_as_float(f2tf(p11));
        }
        s0 += __shfl_xor_sync(0xffffffffu, s0, 1);
        s0 += __shfl_xor_sync(0xffffffffu, s0, 2);
        s1 += __shfl_xor_sync(0xffffffffu, s1, 1);
        s1 += __shfl_xor_sync(0xffffffffu, s1, 2);
        l0s = l0s*c0 + s0;  m0s = mn0;
        l1s = l1s*c1 + s1;  m1s = mn1;

        #pragma unroll
        for (int nj = 0; nj < 8; nj++) {
            o[nj][0] *= c0; o[nj][1] *= c0;
            o[nj][2] *= c1; o[nj][3] *= c1;
        }

        // O += P @ V  — P from registers (permuted key slots)
        #pragma unroll
        for (int nj = 0; nj < 8; nj++) {
            uint32_t pa[4] = { __float_as_uint(sacc[nj][0]),
                               __float_as_uint(sacc[nj][2]),
                               __float_as_uint(sacc[nj][1]),
                               __float_as_uint(sacc[nj][3]) };
            const uint32_t* v0 = (const uint32_t*)(Vs + (nj*8 + 2*tc)*VP);
            const uint32_t* v1 = v0 + VP;
            #pragma unroll
            for (int njo = 0; njo < 8; njo++) {
                uint32_t vb[2] = { v0[njo*8 + gr], v1[njo*8 + gr] };
                mma_tf32(o[njo], pa, vb);
            }
        }
    }

    // Normalize and write
    {
        const int row0 = wid*16 + gr;
        const float inv0 = 1.f / l0s;
        const float inv1 = 1.f / l1s;
        #pragma unroll
        for (int nj = 0; nj < 8; nj++) {
            const int col = nj*8 + 2*tc;
            *(float2*)(Og + (size_t)(m0 + row0)*HDD + col) =
                make_float2(o[nj][0]*inv0, o[nj][1]*inv0);
            *(float2*)(Og + (size_t)(m0 + row0 + 8)*HDD + col) =
                make_float2(o[nj][2]*inv1, o[nj][3]*inv1);
        }
    }
}

// ---------------------------------------------------------------------------
extern "C" void kernel_launch(void* const* d_in, const int* in_sizes, int n_in,
                              void* d_out, int out_size)
{
    const float* query = (const float*)d_in[0];
    const float* Wq = (const float*)d_in[1];
    const float* bq = (const float*)d_in[2];
    const float* Wk = (const float*)d_in[3];
    const float* bk = (const float*)d_in[4];
    const float* Wv = (const float*)d_in[5];
    const float* bv = (const float*)d_in[6];
    const float* Wo = (const float*)d_in[7];
    const float* bo = (const float*)d_in[8];
    const float* Wm1 = (const float*)d_in[9];
    const float* bm1 = (const float*)d_in[10];
    const float* Wm2 = (const float*)d_in[11];
    const float* bm2 = (const float*)d_in[12];
    const float* dop = (const float*)d_in[13];
    const float* ser = (const float*)d_in[14];
    const float* nor = (const float*)d_in[15];
    const float* ace = (const float*)d_in[16];
    const float* asc = (const float*)d_in[17];
    const float* abi = (const float*)d_in[18];
    float* out = (float*)d_out;

    float *q, *k, *v, *hid, *x;
    float *wq, *wk, *wv, *wo, *wm1, *wm2, *qr;
    cudaGetSymbolAddress((void**)&q,   g_q);
    cudaGetSymbolAddress((void**)&k,   g_k);
    cudaGetSymbolAddress((void**)&v,   g_v);
    cudaGetSymbolAddress((void**)&hid, g_hid);
    cudaGetSymbolAddress((void**)&x,   g_x);
    cudaGetSymbolAddress((void**)&wq,  g_wq);
    cudaGetSymbolAddress((void**)&wk,  g_wk);
    cudaGetSymbolAddress((void**)&wv,  g_wv);
    cudaGetSymbolAddress((void**)&wo,  g_wo);
    cudaGetSymbolAddress((void**)&wm1, g_wm1);
    cudaGetSymbolAddress((void**)&wm2, g_wm2);
    cudaGetSymbolAddress((void**)&qr,  g_qr);

    static int attrs_set = 0;
    if (!attrs_set) {
        cudaFuncSetAttribute(attn_mma_kernel,
            cudaFuncAttributeMaxDynamicSharedMemorySize, ATT_SMEM_BYTES);
        cudaFuncSetAttribute(gemm_mma_kernel,
            cudaFuncAttributeMaxDynamicSharedMemorySize, GEMM_SMEM_BYTES);
        attrs_set = 1;
    }

    const int M = BB * SS;          // 4096
    dim3 blk(256);

    // Prepass: round all GEMM operands to tf32 in one launch
    round_all_kernel<<<(SEG_TOT + 255)/256, 256>>>(
        Wq, Wk, Wv, Wo, Wm1, Wm2, query,
        wq, wk, wv, wo, wm1, wm2, qr);

    // Q, K, V projections (epilogue emits tf32 bits; Q pre-scaled by HD^-0.5)
    {
        dim3 grid(DD/128, M/128);
        gemm_mma_kernel<<<grid, blk, GEMM_SMEM_BYTES>>>(
            qr, wq, bq, q, M, DD, DD, 0, 1, 0.125f, 0,
            nullptr, nullptr, nullptr, nullptr, nullptr, nullptr);
        gemm_mma_kernel<<<grid, blk, GEMM_SMEM_BYTES>>>(
            qr, wk, bk, k, M, DD, DD, 0, 1, 1.0f, 0,
            nullptr, nullptr, nullptr, nullptr, nullptr, nullptr);
        gemm_mma_kernel<<<grid, blk, GEMM_SMEM_BYTES>>>(
            qr, wv, bv, v, M, DD, DD, 0, 1, 1.0f, 0,
            nullptr, nullptr, nullptr, nullptr, nullptr, nullptr);
    }

    // MLP1 overlaps nothing but is independent of attention; order: attention
    // must precede MLP2 (gate epilogue reads g_attn).
    {
        dim3 grid1(DM/128, M/128);
        gemm_mma_kernel<<<grid1, blk, GEMM_SMEM_BYTES>>>(
            qr, wm1, bm1, hid, M, DM, DD, 1, 0, 1.0f, 0,
            nullptr, nullptr, nullptr, nullptr, nullptr, nullptr);
    }

    // Attention
    {
        dim3 grid(SS/128, BB*HH);
        attn_mma_kernel<<<grid, blk, ATT_SMEM_BYTES>>>();
    }

    // MLP2 + fused gate/combine epilogue -> g_x (tf32 bits)
    {
        dim3 grid2(DD/128, M/128);
        gemm_mma_kernel<<<grid2, blk, GEMM_SMEM_BYTES>>>(
            hid, wm2, bm2, x, M, DD, DM, 0, 0, 0.f, 1,
            dop, ser, nor, ace, asc, abi);
    }

    // Output projection -> d_out (fp32 out)
    {
        dim3 grid(DD/128, M/128);
        gemm_mma_kernel<<<grid, blk, GEMM_SMEM_BYTES>>>(
            x, wo, bo, out, M, DD, DD, 0, 0, 0.f, 0,
            nullptr, nullptr, nullptr, nullptr, nullptr, nullptr);
    }
}

// round 11
// speedup vs baseline: 1.0003x; 1.0003x over previous
#include <cuda_runtime.h>
#include <cstdint>
#include <cstddef>

// Problem constants
#define BB 2
#define SS 2048
#define DD 1024
#define HH 16
#define HDD 64
#define DM 256  // D/4

// Scratch (device globals — no runtime allocation allowed)
// g_q: tf32 bits pre-scaled by 0.125; g_k/g_v: tf32 bits; g_hid/g_x: tf32 bits.
__device__ float g_q[BB*HH*SS*HDD];
__device__ float g_k[BB*HH*SS*HDD];
__device__ float g_v[BB*HH*SS*HDD];
__device__ float g_attn[BB*HH*SS*HDD];
__device__ float g_hid[BB*SS*DM];
__device__ float g_x[BB*SS*DD];
// tf32-rounded operands (prepass)
__device__ float g_wq[DD*DD];
__device__ float g_wk[DD*DD];
__device__ float g_wv[DD*DD];
__device__ float g_wo[DD*DD];
__device__ float g_wm1[DM*DD];
__device__ float g_wm2[DD*DM];
__device__ float g_qr[BB*SS*DD];

// ===========================================================================
// Helpers (arch-agnostic PTX only: mma.sync tf32, cp.async — no tcgen05!)
// ===========================================================================
__device__ __forceinline__ uint32_t smem_u32(const void* p) {
    uint32_t a;
    asm("{ .reg .u64 t; cvta.to.shared.u64 t, %1; cvt.u32.u64 %0, t; }"
        : "=r"(a) : "l"(p));
    return a;
}

__device__ __forceinline__ uint32_t f2tf(float f) {
    uint32_t u;
    asm("cvt.rna.tf32.f32 %0, %1;" : "=r"(u) : "f"(f));
    return u;
}

// D += A @ B  (m16n8k8 tf32, A row-major, B col-major)
__device__ __forceinline__ void mma_tf32(float (&d)[4], const uint32_t (&a)[4],
                                         const uint32_t (&b)[2]) {
    asm volatile(
        "mma.sync.aligned.m16n8k8.row.col.f32.tf32.tf32.f32 "
        "{%0,%1,%2,%3}, {%4,%5,%6,%7}, {%8,%9}, {%0,%1,%2,%3};"
        : "+f"(d[0]), "+f"(d[1]), "+f"(d[2]), "+f"(d[3])
        : "r"(a[0]), "r"(a[1]), "r"(a[2]), "r"(a[3]), "r"(b[0]), "r"(b[1]));
}

__device__ __forceinline__ void cp16(uint32_t dst, const void* src) {
    asm volatile("cp.async.ca.shared.global [%0], [%1], 16;"
                 :: "r"(dst), "l"(src));
}
#define CP_COMMIT() asm volatile("cp.async.commit_group;" ::: "memory")
#define CP_WAIT1()  asm volatile("cp.async.wait_group 1;"  ::: "memory")
#define CP_WAIT0()  asm volatile("cp.async.wait_group 0;"  ::: "memory")

// ===========================================================================
// Prepass: round 7 fp32 arrays to tf32 bits (RNA) in ONE launch.
// Segments (uint4 units): wq,wk,wv,wo (256K each), wm1,wm2 (64K), qr (1M).
// ===========================================================================
#define SEG_W  (DD*DD/4)     // 262144
#define SEG_M  (DM*DD/4)     // 65536
#define SEG_Q  (BB*SS*DD/4)  // 1048576
#define SEG_TOT (4*SEG_W + 2*SEG_M + SEG_Q)

__global__ void round_all_kernel(
    const float* __restrict__ s0, const float* __restrict__ s1,
    const float* __restrict__ s2, const float* __restrict__ s3,
    const float* __restrict__ s4, const float* __restrict__ s5,
    const float* __restrict__ s6,
    float* __restrict__ d0, float* __restrict__ d1,
    float* __restrict__ d2, float* __restrict__ d3,
    float* __restrict__ d4, float* __restrict__ d5,
    float* __restrict__ d6)
{
    int i = blockIdx.x * blockDim.x + threadIdx.x;
    if (i >= SEG_TOT) return;
    const float* src; float* dst;
    if      (i < SEG_W)              { src = s0; dst = d0; }
    else if (i < 2*SEG_W)            { src = s1; dst = d1; i -= SEG_W; }
    else if (i < 3*SEG_W)            { src = s2; dst = d2; i -= 2*SEG_W; }
    else if (i < 4*SEG_W)            { src = s3; dst = d3; i -= 3*SEG_W; }
    else if (i < 4*SEG_W + SEG_M)    { src = s4; dst = d4; i -= 4*SEG_W; }
    else if (i < 4*SEG_W + 2*SEG_M)  { src = s5; dst = d5; i -= 4*SEG_W + SEG_M; }
    else                             { src = s6; dst = d6; i -= 4*SEG_W + 2*SEG_M; }
    float4 v = ((const float4*)src)[i];
    ((uint4*)dst)[i] = make_uint4(f2tf(v.x), f2tf(v.y), f2tf(v.z), f2tf(v.w));
}

// ===========================================================================
// tf32 MMA GEMM: C[M,N] = A[M,K] @ W[N,K]^T + bias[N]
// A and W PRE-ROUNDED tf32 bits. 128x128 CTA tile, 8 warps (32x64 warp tile),
// BK=32 double-buffered cp.async (dynamic smem 64KB, 2 CTAs/SM), vectorized
// LDS.128 fragment loads via k-permutation.
// relu: ReLU. split: head-split layout. conv != 0: store f2tf(val*conv).
// gate: epilogue x = (attn*asc + abi)*(1 + mod*gate4) -> tf32 bits (C=g_x).
// ===========================================================================
#define GBK 32
#define GTILE (128*GBK)
#define GEMM_SMEM_BYTES (4*GTILE*4)   // As[2] + Bs[2]

__global__ void __launch_bounds__(256, 2) gemm_mma_kernel(
    const float* __restrict__ A, const float* __restrict__ W,
    const float* __restrict__ bias, float* __restrict__ C,
    int M, int N, int K, int relu, int split, float conv, int gate,
    const float* __restrict__ dop, const float* __restrict__ ser,
    const float* __restrict__ nor, const float* __restrict__ ace,
    const float* __restrict__ asc, const float* __restrict__ abi)
{
    extern __shared__ float gsm[];
    float* As0 = gsm;
    float* As1 = gsm + GTILE;
    float* Bs0 = gsm + 2*GTILE;
    float* Bs1 = gsm + 3*GTILE;

    const int tid = threadIdx.x;
    const int wid = tid >> 5;
    const int lane = tid & 31;
    const int gr = lane >> 2;       // group row 0..7
    const int tc = lane & 3;        // thread col 0..3
    const int warp_m = wid & 3;     // 4 warps along M
    const int warp_n = wid >> 2;    // 2 warps along N
    const int m0 = blockIdx.y << 7;
    const int n0 = blockIdx.x << 7;

    const uint32_t sA[2] = { smem_u32(As0), smem_u32(As1) };
    const uint32_t sB[2] = { smem_u32(Bs0), smem_u32(Bs1) };
    const float* Abuf[2] = { As0, As1 };
    const float* Bbuf[2] = { Bs0, Bs1 };

    float acc[2][8][4];
    #pragma unroll
    for (int mi = 0; mi < 2; mi++)
        #pragma unroll
        for (int nj = 0; nj < 8; nj++)
            #pragma unroll
            for (int q = 0; q < 4; q++) acc[mi][nj][q] = 0.f;

    const int KB = K >> 5;

    // 128 rows x 32 floats per matrix = 1024 cp16 -> 4 per thread per matrix
    auto issue = [&](int kb, int buf) {
        #pragma unroll
        for (int i = 0; i < 4; i++) {
            const int ch = tid + (i << 8);       // 0..1023
            const int row = ch >> 3, c8 = ch & 7;
            cp16(sA[buf] + (uint32_t)(row*GBK + c8*4)*4,
                 A + (size_t)(m0 + row)*K + kb*GBK + c8*4);
            cp16(sB[buf] + (uint32_t)(row*GBK + c8*4)*4,
                 W + (size_t)(n0 + row)*K + kb*GBK + c8*4);
        }
    };

    issue(0, 0);
    CP_COMMIT();

    for (int kb = 0; kb < KB; kb++) {
        const int buf = kb & 1;
        if (kb + 1 < KB) issue(kb + 1, buf ^ 1);
        CP_COMMIT();
        CP_WAIT1();
        __syncthreads();

        const uint32_t* a_s = (const uint32_t*)Abuf[buf];
        const uint32_t* b_s = (const uint32_t*)Bbuf[buf];

        #pragma unroll
        for (int ks = 0; ks < GBK; ks += 16) {
            uint4 a4[2][2];
            #pragma unroll
            for (int mi = 0; mi < 2; mi++) {
                const int r = warp_m*32 + mi*16 + gr;
                a4[mi][0] = *(const uint4*)(a_s + r*GBK + ks + 4*tc);
                a4[mi][1] = *(const uint4*)(a_s + (r+8)*GBK + ks + 4*tc);
            }
            uint32_t af0[2][4], af1[2][4];
            #pragma unroll
            for (int mi = 0; mi < 2; mi++) {
                af0[mi][0] = a4[mi][0].x; af0[mi][1] = a4[mi][1].x;
                af0[mi][2] = a4[mi][0].z; af0[mi][3] = a4[mi][1].z;
                af1[mi][0] = a4[mi][0].y; af1[mi][1] = a4[mi][1].y;
                af1[mi][2] = a4[mi][0].w; af1[mi][3] = a4[mi][1].w;
            }
            #pragma unroll
            for (int nj = 0; nj < 8; nj++) {
                const int n = warp_n*64 + nj*8 + gr;
                uint4 b4 = *(const uint4*)(b_s + n*GBK + ks + 4*tc);
                uint32_t bf0[2] = { b4.x, b4.z };
                uint32_t bf1[2] = { b4.y, b4.w };
                mma_tf32(acc[0][nj], af0[0], bf0);
                mma_tf32(acc[1][nj], af0[1], bf0);
                mma_tf32(acc[0][nj], af1[0], bf1);
                mma_tf32(acc[1][nj], af1[1], bf1);
            }
        }
        __syncthreads();
    }

    // Epilogue
    float gate4 = 0.f, ascv = 0.f, abiv = 0.f;
    if (gate) {
        gate4 = 0.25f * (dop[0] + ser[0] + nor[0] + ace[0]);
        ascv = asc[0];
        abiv = abi[0];
    }
    #pragma unroll
    for (int mi = 0; mi < 2; mi++) {
        const int row = m0 + warp_m*32 + mi*16 + gr;
        #pragma unroll
        for (int nj = 0; nj < 8; nj++) {
            const int col = n0 + warp_n*64 + nj*8 + 2*tc;
            const float b0 = bias[col], b1 = bias[col+1];
            float2 v0 = make_float2(acc[mi][nj][0] + b0, acc[mi][nj][1] + b1);
            float2 v1 = make_float2(acc[mi][nj][2] + b0, acc[mi][nj][3] + b1);
            if (relu) {
                v0.x = fmaxf(v0.x, 0.f); v0.y = fmaxf(v0.y, 0.f);
                v1.x = fmaxf(v1.x, 0.f); v1.y = fmaxf(v1.y, 0.f);
            }
            if (gate) {
                // mod -> x = (attn*asc + abi) * (1 + mod*gate4), tf32 bits
                const int b = row >> 11, s = row & (SS - 1);
                const int h = col >> 6, hd = col & 63;
                const int rb = (row+8) >> 11, rs = (row+8) & (SS - 1);
                float2 a0 = *(const float2*)(g_attn +
                    (((size_t)(b*HH + h))*SS + s)*HDD + hd);
                float2 a1 = *(const float2*)(g_attn +
                    (((size_t)(rb*HH + h))*SS + rs)*HDD + hd);
                v0.x = __uint_as_float(f2tf((a0.x*ascv + abiv)*(1.f + v0.x*gate4)));
                v0.y = __uint_as_float(f2tf((a0.y*ascv + abiv)*(1.f + v0.y*gate4)));
                v1.x = __uint_as_float(f2tf((a1.x*ascv + abiv)*(1.f + v1.x*gate4)));
                v1.y = __uint_as_float(f2tf((a1.y*ascv + abiv)*(1.f + v1.y*gate4)));
            } else if (conv != 0.f) {
                v0.x = __uint_as_float(f2tf(v0.x * conv));
                v0.y = __uint_as_float(f2tf(v0.y * conv));
                v1.x = __uint_as_float(f2tf(v1.x * conv));
                v1.y = __uint_as_float(f2tf(v1.y * conv));
            }
            if (split) {
                const int b = row >> 11, s = row & (SS - 1);
                const int h = col >> 6, hd = col & 63;
                float* d0 = C + (((size_t)(b*HH + h))*SS + s)*HDD + hd;
                const int rb = (row+8) >> 11, rs = (row+8) & (SS - 1);
                float* d1 = C + (((size_t)(rb*HH + h))*SS + rs)*HDD + hd;
                *(float2*)d0 = v0;
                *(float2*)d1 = v1;
            } else {
                *(float2*)(C + (size_t)row*N + col) = v0;
                *(float2*)(C + (size_t)(row+8)*N + col) = v1;
            }
        }
    }
}

// ===========================================================================
// Flash attention, tf32 MMA, P fully register-resident (no P smem),
// vectorized K fragment loads, cp.async double buffer, 1 sync per tile.
// smem: Kd[2][64*80]  Vd[2][64*68]  (strides conflict-free)
// ===========================================================================
#define KP 80
#define VP 68
#define KTILE (64*KP)
#define VTILE (64*VP)
#define ATT_SMEM_BYTES ((2*KTILE + 2*VTILE)*4)

__global__ void __launch_bounds__(256, 2) attn_mma_kernel()
{
    extern __shared__ float sm[];
    float* Kd = sm;                 // [2][64*KP] tf32 bits
    float* Vd = sm + 2*KTILE;       // [2][64*VP] tf32 bits

    const int tid = threadIdx.x;
    const int wid = tid >> 5;
    const int lane = tid & 31;
    const int gr = lane >> 2;
    const int tc = lane & 3;

    const int bh = blockIdx.y;
    const int m0 = blockIdx.x << 7;
    const float* Qg = g_q + (size_t)bh * SS * HDD;
    const float* Kg = g_k + (size_t)bh * SS * HDD;
    const float* Vg = g_v + (size_t)bh * SS * HDD;
    float*       Og = g_attn + (size_t)bh * SS * HDD;

    const uint32_t sK = smem_u32(Kd);
    const uint32_t sV = smem_u32(Vd);

    auto issue_kv = [&](int kt, int buf) {
        const int kbase = kt << 6;
        #pragma unroll
        for (int i = 0; i < 4; i++) {
            const int ch = tid + (i << 8);          // 0..1023
            const int row = ch >> 4, c16 = ch & 15;
            const size_t soff = (size_t)(kbase + row)*HDD + c16*4;
            cp16(sK + (uint32_t)(buf*KTILE + row*KP + c16*4)*4, Kg + soff);
            cp16(sV + (uint32_t)(buf*VTILE + row*VP + c16*4)*4, Vg + soff);
        }
    };

    // Q fragments (tf32 bits, pre-scaled), permuted hd mapping
    uint32_t qa[8][4];
    {
        const uint32_t* q0 = (const uint32_t*)(Qg + (size_t)(m0 + wid*16 + gr) * HDD);
        const uint32_t* q1 = q0 + 8 * HDD;
        #pragma unroll
        for (int g = 0; g < 4; g++) {
            uint4 ua = *(const uint4*)(q0 + 16*g + 4*tc);
            uint4 ub = *(const uint4*)(q1 + 16*g + 4*tc);
            qa[2*g][0]   = ua.x; qa[2*g+1][0] = ua.y;
            qa[2*g][2]   = ua.z; qa[2*g+1][2] = ua.w;
            qa[2*g][1]   = ub.x; qa[2*g+1][1] = ub.y;
            qa[2*g][3]   = ub.z; qa[2*g+1][3] = ub.w;
        }
    }

    float m0s = -1e30f, m1s = -1e30f, l0s = 0.f, l1s = 0.f;
    float o[8][4];
    #pragma unroll
    for (int nj = 0; nj < 8; nj++)
        #pragma unroll
        for (int q = 0; q < 4; q++) o[nj][q] = 0.f;

    issue_kv(0, 0);
    CP_COMMIT();

    const int NT = SS / 64;
    for (int kt = 0; kt < NT; kt++) {
        const int buf = kt & 1;
        CP_WAIT0();
        __syncthreads();
        if (kt + 1 < NT) { issue_kv(kt + 1, buf ^ 1); CP_COMMIT(); }

        const float* Ks = Kd + buf*KTILE;
        const float* Vs = Vd + buf*VTILE;

        // S = Q @ K^T (warp: 16 rows x 64 keys), vectorized B loads
        float sacc[8][4];
        #pragma unroll
        for (int nj = 0; nj < 8; nj++)
            #pragma unroll
            for (int q = 0; q < 4; q++) sacc[nj][q] = 0.f;
        #pragma unroll
        for (int nj = 0; nj < 8; nj++) {
            const uint32_t* krow = (const uint32_t*)(Ks + (nj*8 + gr)*KP);
            #pragma unroll
            for (int g = 0; g < 4; g++) {
                uint4 kb = *(const uint4*)(krow + 16*g + 4*tc);
                uint32_t bf0[2] = { kb.x, kb.z };
                uint32_t bf1[2] = { kb.y, kb.w };
                mma_tf32(sacc[nj], qa[2*g],   bf0);
                mma_tf32(sacc[nj], qa[2*g+1], bf1);
            }
        }

        // Register online softmax (rows gr -> elems 0,1; gr+8 -> 2,3)
        float mx0 = -1e30f, mx1 = -1e30f;
        #pragma unroll
        for (int nj = 0; nj < 8; nj++) {
            mx0 = fmaxf(mx0, fmaxf(sacc[nj][0], sacc[nj][1]));
            mx1 = fmaxf(mx1, fmaxf(sacc[nj][2], sacc[nj][3]));
        }
        mx0 = fmaxf(mx0, __shfl_xor_sync(0xffffffffu, mx0, 1));
        mx0 = fmaxf(mx0, __shfl_xor_sync(0xffffffffu, mx0, 2));
        mx1 = fmaxf(mx1, __shfl_xor_sync(0xffffffffu, mx1, 1));
        mx1 = fmaxf(mx1, __shfl_xor_sync(0xffffffffu, mx1, 2));

        const float mn0 = fmaxf(m0s, mx0);
        const float mn1 = fmaxf(m1s, mx1);
        const float c0 = __expf(m0s - mn0);
        const float c1 = __expf(m1s - mn1);
        float s0 = 0.f, s1 = 0.f;

        #pragma unroll
        for (int nj = 0; nj < 8; nj++) {
            const float p00 = __expf(sacc[nj][0] - mn0);
            const float p01 = __expf(sacc[nj][1] - mn0);
            const float p10 = __expf(sacc[nj][2] - mn1);
            const float p11 = __expf(sacc[nj][3] - mn1);
            s0 += p00 + p01;
            s1 += p10 + p11;
            sacc[nj][0] = __uint_as_float(f2tf(p00));
            sacc[nj][1] = __uint_as_float(f2tf(p01));
            sacc[nj][2] = __uint_as_float(f2tf(p10));
            sacc[nj][3] = __uint_as_float(f2tf(p11));
        }
        s0 += __shfl_xor_sync(0xffffffffu, s0, 1);
        s0 += __shfl_xor_sync(0xffffffffu, s0, 2);
        s1 += __shfl_xor_sync(0xffffffffu, s1, 1);
        s1 += __shfl_xor_sync(0xffffffffu, s1, 2);
        l0s = l0s*c0 + s0;  m0s = mn0;
        l1s = l1s*c1 + s1;  m1s = mn1;

        #pragma unroll
        for (int nj = 0; nj < 8; nj++) {
            o[nj][0] *= c0; o[nj][1] *= c0;
            o[nj][2] *= c1; o[nj][3] *= c1;
        }

        // O += P @ V  — P from registers (permuted key slots)
        #pragma unroll
        for (int nj = 0; nj < 8; nj++) {
            uint32_t pa[4] = { __float_as_uint(sacc[nj][0]),
                               __float_as_uint(sacc[nj][2]),
                               __float_as_uint(sacc[nj][1]),
                               __float_as_uint(sacc[nj][3]) };
            const uint32_t* v0 = (const uint32_t*)(Vs + (nj*8 + 2*tc)*VP);
            const uint32_t* v1 = v0 + VP;
            #pragma unroll
            for (int njo = 0; njo < 8; njo++) {
                uint32_t vb[2] = { v0[njo*8 + gr], v1[njo*8 + gr] };
                mma_tf32(o[njo], pa, vb);
            }
        }
    }

    // Normalize and write
    {
        const int row0 = wid*16 + gr;
        const float inv0 = 1.f / l0s;
        const float inv1 = 1.f / l1s;
        #pragma unroll
        for (int nj = 0; nj < 8; nj++) {
            const int col = nj*8 + 2*tc;
            *(float2*)(Og + (size_t)(m0 + row0)*HDD + col) =
                make_float2(o[nj][0]*inv0, o[nj][1]*inv0);
            *(float2*)(Og + (size_t)(m0 + row0 + 8)*HDD + col) =
                make_float2(o[nj][2]*inv1, o[nj][3]*inv1);
        }
    }
}

// ---------------------------------------------------------------------------
extern "C" void kernel_launch(void* const* d_in, const int* in_sizes, int n_in,
                              void* d_out, int out_size)
{
    const float* query = (const float*)d_in[0];
    const float* Wq = (const float*)d_in[1];
    const float* bq = (const float*)d_in[2];
    const float* Wk = (const float*)d_in[3];
    const float* bk = (const float*)d_in[4];
    const float* Wv = (const float*)d_in[5];
    const float* bv = (const float*)d_in[6];
    const float* Wo = (const float*)d_in[7];
    const float* bo = (const float*)d_in[8];
    const float* Wm1 = (const float*)d_in[9];
    const float* bm1 = (const float*)d_in[10];
    const float* Wm2 = (const float*)d_in[11];
    const float* bm2 = (const float*)d_in[12];
    const float* dop = (const float*)d_in[13];
    const float* ser = (const float*)d_in[14];
    const float* nor = (const float*)d_in[15];
    const float* ace = (const float*)d_in[16];
    const float* asc = (const float*)d_in[17];
    const float* abi = (const float*)d_in[18];
    float* out = (float*)d_out;

    float *q, *k, *v, *hid, *x;
    float *wq, *wk, *wv, *wo, *wm1, *wm2, *qr;
    cudaGetSymbolAddress((void**)&q,   g_q);
    cudaGetSymbolAddress((void**)&k,   g_k);
    cudaGetSymbolAddress((void**)&v,   g_v);
    cudaGetSymbolAddress((void**)&hid, g_hid);
    cudaGetSymbolAddress((void**)&x,   g_x);
    cudaGetSymbolAddress((void**)&wq,  g_wq);
    cudaGetSymbolAddress((void**)&wk,  g_wk);
    cudaGetSymbolAddress((void**)&wv,  g_wv);
    cudaGetSymbolAddress((void**)&wo,  g_wo);
    cudaGetSymbolAddress((void**)&wm1, g_wm1);
    cudaGetSymbolAddress((void**)&wm2, g_wm2);
    cudaGetSymbolAddress((void**)&qr,  g_qr);

    static int attrs_set = 0;
    if (!attrs_set) {
        cudaFuncSetAttribute(attn_mma_kernel,
            cudaFuncAttributeMaxDynamicSharedMemorySize, ATT_SMEM_BYTES);
        cudaFuncSetAttribute(gemm_mma_kernel,
            cudaFuncAttributeMaxDynamicSharedMemorySize, GEMM_SMEM_BYTES);
        attrs_set = 1;
    }

    const int M = BB * SS;          // 4096
    dim3 blk(256);

    // Prepass: round all GEMM operands to tf32 in one launch
    round_all_kernel<<<(SEG_TOT + 255)/256, 256>>>(
        Wq, Wk, Wv, Wo, Wm1, Wm2, query,
        wq, wk, wv, wo, wm1, wm2, qr);

    // Q, K, V projections (epilogue emits tf32 bits; Q pre-scaled by HD^-0.5)
    {
        dim3 grid(DD/128, M/128);
        gemm_mma_kernel<<<grid, blk, GEMM_SMEM_BYTES>>>(
            qr, wq, bq, q, M, DD, DD, 0, 1, 0.125f, 0,
            nullptr, nullptr, nullptr, nullptr, nullptr, nullptr);
        gemm_mma_kernel<<<grid, blk, GEMM_SMEM_BYTES>>>(
            qr, wk, bk, k, M, DD, DD, 0, 1, 1.0f, 0,
            nullptr, nullptr, nullptr, nullptr, nullptr, nullptr);
        gemm_mma_kernel<<<grid, blk, GEMM_SMEM_BYTES>>>(
            qr, wv, bv, v, M, DD, DD, 0, 1, 1.0f, 0,
            nullptr, nullptr, nullptr, nullptr, nullptr, nullptr);
    }

    // MLP1 overlaps nothing but is independent of attention; order: attention
    // must precede MLP2 (gate epilogue reads g_attn).
    {
        dim3 grid1(DM/128, M/128);
        gemm_mma_kernel<<<grid1, blk, GEMM_SMEM_BYTES>>>(
            qr, wm1, bm1, hid, M, DM, DD, 1, 0, 1.0f, 0,
            nullptr, nullptr, nullptr, nullptr, nullptr, nullptr);
    }

    // Attention
    {
        dim3 grid(SS/128, BB*HH);
        attn_mma_kernel<<<grid, blk, ATT_SMEM_BYTES>>>();
    }

    // MLP2 + fused gate/combine epilogue -> g_x (tf32 bits)
    {
        dim3 grid2(DD/128, M/128);
        gemm_mma_kernel<<<grid2, blk, GEMM_SMEM_BYTES>>>(
            hid, wm2, bm2, x, M, DD, DM, 0, 0, 0.f, 1,
            dop, ser, nor, ace, asc, abi);
    }

    // Output projection -> d_out (fp32 out)
    {
        dim3 grid(DD/128, M/128);
        gemm_mma_kernel<<<grid, blk, GEMM_SMEM_BYTES>>>(
            x, wo, bo, out, M, DD, DD, 0, 0, 0.f, 0,
            nullptr, nullptr, nullptr, nullptr, nullptr, nullptr);
    }
}